// round 12
// baseline (speedup 1.0000x reference)
#include <cuda_runtime.h>
#include <cuda_bf16.h>
#include <math.h>

// Problem constants: x [16, 256, 128, 128] fp32, w [1, 2, 7, 7] fp32
// out [16, 1, 128, 128] fp32
#define B_  16
#define C_  256
#define H_  128
#define W_  128
#define HW_ (H_ * W_)          // 16384
#define HW4_ (HW_ / 4)         // 4096 float4 groups per plane
#define NCHUNK 4
#define CPC (C_ / NCHUNK)      // 64 channels per chunk

// Reduce work items: 1024 = 16 batches x 4 chunks x 16 slices (256 groups each)
#define NITEM   1024
#define NBLK    736            // grid; all resident at occ>=5/SM (740 capacity)
#define ROUND2  (NITEM - NBLK) // 288 second-round items (blocks 0..287)

// Conv tiling: 16 rows x 32 cols -> 512 tiles, ticket-ordered by batch.
#define HT   16
#define TRR  (HT + 6)          // 22 input rows incl. vertical halo
#define GT   10                // 8 groups + 2 halo groups
#define NIT  (2 * TRR * GT)    // 440 staging items per tile
#define NTILE 512

// Scratch: per-chunk partials [chunk][B][2][HW] = 8 MB
__device__ float g_part[NCHUNK * B_ * 2 * HW_];
// Sync state (reset each launch via cudaMemsetAsync): per-batch done counters + tile ticket
__device__ int g_sync[B_ + 1];   // [0..15] = batch counters, [16] = tile ticket

// ---------------------------------------------------------------------------
// One reduce item: 256 float4 groups x 64 channels of (batch, chunk, slice).
// Identical per-thread structure to the proven 41us chunked reduce.
// ---------------------------------------------------------------------------
__device__ __forceinline__ void do_reduce_item(const float* __restrict__ x, int item) {
    int b     = item >> 6;          // batch
    int r     = item & 63;
    int chunk = r & 3;
    int slice = r >> 2;             // 0..15
    int sp4   = slice * 256 + threadIdx.x;

    const float4* base = reinterpret_cast<const float4*>(x)
                       + (size_t)b * C_ * HW4_ + (size_t)chunk * CPC * HW4_ + sp4;

    float4 sum = make_float4(0.f, 0.f, 0.f, 0.f);
    float4 mx  = make_float4(-INFINITY, -INFINITY, -INFINITY, -INFINITY);

    #pragma unroll 8
    for (int c = 0; c < CPC; ++c) {
        float4 v = __ldcs(base + c * HW4_);          // streaming, evict-first
        sum.x += v.x; sum.y += v.y; sum.z += v.z; sum.w += v.w;
        mx.x = fmaxf(mx.x, v.x); mx.y = fmaxf(mx.y, v.y);
        mx.z = fmaxf(mx.z, v.z); mx.w = fmaxf(mx.w, v.w);
    }

    float4* p_sum = reinterpret_cast<float4*>(g_part)
                  + (size_t)chunk * B_ * 2 * HW4_ + (size_t)b * 2 * HW4_ + sp4;
    *p_sum          = sum;
    *(p_sum + HW4_) = mx;

    __threadfence();                 // make this thread's stores device-visible
    __syncthreads();                 // all threads' fences done
    if (threadIdx.x == 0) atomicAdd(&g_sync[b], 1);   // publish
}

// ---------------------------------------------------------------------------
// One conv tile: combine 4-chunk partials into smem (halo zero-padded),
// 7x7 2-ch conv + sigmoid, 4-wide register blocked. (R10 fused body.)
// ---------------------------------------------------------------------------
__device__ __forceinline__ void do_conv_tile(int t, const float* ws,
                                             float4 (*sm)[TRR][GT],
                                             float* __restrict__ out) {
    int b   = t >> 5;
    int rem = t & 31;
    int ht  = rem >> 2;
    int wt  = rem & 3;
    int h0  = ht * HT;
    int w0g = wt * 8;
    int gb  = w0g - 1;

    const size_t cs = (size_t)B_ * 2 * HW4_;
    const float inv = 1.0f / (float)C_;
    const float4* pb = reinterpret_cast<const float4*>(g_part) + (size_t)b * 2 * HW4_;

    // Staging: 440 items, <=2/thread, loads batched
    {
        float4 regs[2][4];
        int    pl[2], rr[2], jj[2];
        bool   valid[2], own[2];

        #pragma unroll
        for (int k = 0; k < 2; ++k) {
            int i = threadIdx.x + k * 256;
            own[k] = (i < NIT);
            if (own[k]) {
                int plane = i / (TRR * GT);
                int r2    = i - plane * (TRR * GT);
                int rr_   = r2 / GT;
                int j     = r2 - rr_ * GT;
                int hh    = h0 - 3 + rr_;
                int gg    = gb + j;
                pl[k] = plane; rr[k] = rr_; jj[k] = j;
                valid[k] = ((unsigned)hh < (unsigned)H_) && ((unsigned)gg < 32u);
                const float4* p = pb + (size_t)plane * HW4_
                                + (valid[k] ? (hh * 32 + gg) : 0);
                #pragma unroll
                for (int c = 0; c < 4; ++c)
                    regs[k][c] = __ldg(p + c * cs);
            }
        }

        #pragma unroll
        for (int k = 0; k < 2; ++k) {
            if (own[k]) {
                float4 v = make_float4(0.f, 0.f, 0.f, 0.f);
                if (valid[k]) {
                    if (pl[k] == 0) {
                        v.x = (regs[k][0].x + regs[k][1].x + regs[k][2].x + regs[k][3].x) * inv;
                        v.y = (regs[k][0].y + regs[k][1].y + regs[k][2].y + regs[k][3].y) * inv;
                        v.z = (regs[k][0].z + regs[k][1].z + regs[k][2].z + regs[k][3].z) * inv;
                        v.w = (regs[k][0].w + regs[k][1].w + regs[k][2].w + regs[k][3].w) * inv;
                    } else {
                        v.x = fmaxf(fmaxf(regs[k][0].x, regs[k][1].x), fmaxf(regs[k][2].x, regs[k][3].x));
                        v.y = fmaxf(fmaxf(regs[k][0].y, regs[k][1].y), fmaxf(regs[k][2].y, regs[k][3].y));
                        v.z = fmaxf(fmaxf(regs[k][0].z, regs[k][1].z), fmaxf(regs[k][2].z, regs[k][3].z));
                        v.w = fmaxf(fmaxf(regs[k][0].w, regs[k][1].w), fmaxf(regs[k][2].w, regs[k][3].w));
                    }
                }
                sm[pl[k]][rr[k]][jj[k]] = v;
            }
        }
    }
    __syncthreads();

    if (threadIdx.x < 128) {
        int r = threadIdx.x >> 3;
        int j = threadIdx.x & 7;

        float acc0 = 0.f, acc1 = 0.f, acc2 = 0.f, acc3 = 0.f;

        #pragma unroll
        for (int ch = 0; ch < 2; ++ch) {
            const float* wp = ws + ch * 49;
            #pragma unroll
            for (int kh = 0; kh < 7; ++kh) {
                float4 lo  = sm[ch][r + kh][j];
                float4 mid = sm[ch][r + kh][j + 1];
                float4 hi  = sm[ch][r + kh][j + 2];
                float v[12] = { lo.x, lo.y, lo.z, lo.w,
                                mid.x, mid.y, mid.z, mid.w,
                                hi.x, hi.y, hi.z, hi.w };
                #pragma unroll
                for (int kw = 0; kw < 7; ++kw) {
                    float wv = wp[kh * 7 + kw];
                    acc0 = fmaf(v[kw + 1], wv, acc0);
                    acc1 = fmaf(v[kw + 2], wv, acc1);
                    acc2 = fmaf(v[kw + 3], wv, acc2);
                    acc3 = fmaf(v[kw + 4], wv, acc3);
                }
            }
        }

        float4 res;
        res.x = 1.0f / (1.0f + __expf(-acc0));
        res.y = 1.0f / (1.0f + __expf(-acc1));
        res.z = 1.0f / (1.0f + __expf(-acc2));
        res.w = 1.0f / (1.0f + __expf(-acc3));
        reinterpret_cast<float4*>(out)[(size_t)b * HW4_ + (h0 + r) * 32 + w0g + j] = res;
    }
}

// ---------------------------------------------------------------------------
// Persistent fused kernel: 736 blocks, ALL resident (launch_bounds min 5/SM ->
// 740 capacity). Round-1: one reduce item each (done ~29.5us; batches 0-11
// complete, partials L2-hot). Blocks 288-735 then conv early batches via
// ticket while blocks 0-287 stream round-2 items. Spin on per-batch counters.
// ---------------------------------------------------------------------------
__global__ __launch_bounds__(256, 5)
void fused_persistent_kernel(const float* __restrict__ x,
                             const float* __restrict__ wgt,
                             float* __restrict__ out) {
    __shared__ float4 sm[2][TRR][GT];
    __shared__ float  ws[98];
    __shared__ int    s_tile;

    if (threadIdx.x < 98) ws[threadIdx.x] = __ldg(wgt + threadIdx.x);

    int bid = blockIdx.x;

    // Reduce phase
    do_reduce_item(x, bid);
    if (bid < ROUND2)
        do_reduce_item(x, NBLK + bid);

    // Conv phase: batch-ordered ticket queue
    for (;;) {
        if (threadIdx.x == 0) s_tile = atomicAdd(&g_sync[B_], 1);
        __syncthreads();
        int t = s_tile;
        if (t >= NTILE) break;

        int tb = t >> 5;                      // tile's batch
        if (threadIdx.x == 0) {
            while (*(volatile int*)&g_sync[tb] < 64) { }   // wait 64 producers
        }
        __syncthreads();
        __threadfence();                      // acquire: no stale partial reads

        do_conv_tile(t, ws, sm, out);
        __syncthreads();                      // sm + s_tile reuse safe
    }
}

extern "C" void kernel_launch(void* const* d_in, const int* in_sizes, int n_in,
                              void* d_out, int out_size) {
    const float* x = (const float*)d_in[0];
    const float* w = (const float*)d_in[1];
    float* out = (float*)d_out;

    // Reset counters + ticket each launch/replay (async memset node, no alloc)
    void* sync_addr = nullptr;
    cudaGetSymbolAddress(&sync_addr, g_sync);
    cudaMemsetAsync(sync_addr, 0, sizeof(int) * (B_ + 1));

    fused_persistent_kernel<<<NBLK, 256>>>(x, w, out);
}

// round 13
// speedup vs baseline: 1.0156x; 1.0156x over previous
#include <cuda_runtime.h>
#include <cuda_bf16.h>
#include <math.h>

// Problem constants: x [16, 256, 128, 128] fp32, w [1, 2, 7, 7] fp32
// out [16, 1, 128, 128] fp32
#define B_  16
#define C_  256
#define H_  128
#define W_  128
#define HW_ (H_ * W_)          // 16384
#define HW4_ (HW_ / 4)         // 4096 float4 groups per plane
#define NCHUNK 4
#define CPC (C_ / NCHUNK)      // 64 channels per chunk

// Reduce: 1024 items = 16 batches x 16 slices x 4 chunks; 512 blocks x 2 items.
#define NBLK  512              // all resident in one wave (cap 740 @ 48 regs)

// Conv tiling: 16 rows x 32 cols -> 512 tiles (1 per block after reduce).
#define HT   16
#define TRR  (HT + 6)          // 22 input rows incl. vertical halo
#define GT   10                // 8 groups + 2 halo groups
#define NIT  (2 * TRR * GT)    // 440 staging items per tile
#define NTILE 512

// Scratch: per-chunk partials [chunk][B][2][HW] = 8 MB
__device__ float g_part[NCHUNK * B_ * 2 * HW_];
// Sync state (reset each launch via cudaMemsetAsync node):
// [0..15] per-batch producer counters (target 64), [16] conv tile ticket
__device__ int g_sync[B_ + 1];

// ---------------------------------------------------------------------------
// One reduce item: 256 float4 groups x 64 channels of (batch, chunk, slice).
// Same per-thread structure as the proven 41.7us/82.5%-DRAM chunked reduce.
// ---------------------------------------------------------------------------
__device__ __forceinline__ void do_reduce_item(const float* __restrict__ x, int item) {
    int b     = item >> 6;          // batch
    int r     = item & 63;
    int chunk = r & 3;
    int slice = r >> 2;             // 0..15
    int sp4   = slice * 256 + threadIdx.x;

    const float4* base = reinterpret_cast<const float4*>(x)
                       + (size_t)b * C_ * HW4_ + (size_t)chunk * CPC * HW4_ + sp4;

    float4 sum = make_float4(0.f, 0.f, 0.f, 0.f);
    float4 mx  = make_float4(-INFINITY, -INFINITY, -INFINITY, -INFINITY);

    #pragma unroll 8
    for (int c = 0; c < CPC; ++c) {
        float4 v = __ldcs(base + c * HW4_);          // streaming, evict-first
        sum.x += v.x; sum.y += v.y; sum.z += v.z; sum.w += v.w;
        mx.x = fmaxf(mx.x, v.x); mx.y = fmaxf(mx.y, v.y);
        mx.z = fmaxf(mx.z, v.z); mx.w = fmaxf(mx.w, v.w);
    }

    float4* p_sum = reinterpret_cast<float4*>(g_part)
                  + (size_t)chunk * B_ * 2 * HW4_ + (size_t)b * 2 * HW4_ + sp4;
    *p_sum          = sum;                           // default st: stays L2
    *(p_sum + HW4_) = mx;
}

// ---------------------------------------------------------------------------
// One conv tile: combine 4-chunk partials (L2-hot) into smem (halo zero-
// padded), 7x7 2-ch conv + sigmoid, 4-wide register blocked. (R10 body.)
// ---------------------------------------------------------------------------
__device__ __forceinline__ void do_conv_tile(int t, const float* ws,
                                             float4 (*sm)[TRR][GT],
                                             float* __restrict__ out) {
    int b   = t >> 5;
    int rem = t & 31;
    int ht  = rem >> 2;
    int wt  = rem & 3;
    int h0  = ht * HT;
    int w0g = wt * 8;
    int gb  = w0g - 1;

    const size_t cs = (size_t)B_ * 2 * HW4_;
    const float inv = 1.0f / (float)C_;
    const float4* pb = reinterpret_cast<const float4*>(g_part) + (size_t)b * 2 * HW4_;

    // Staging: 440 items, <=2/thread, loads batched
    {
        float4 regs[2][4];
        int    pl[2], rr[2], jj[2];
        bool   valid[2], own[2];

        #pragma unroll
        for (int k = 0; k < 2; ++k) {
            int i = threadIdx.x + k * 256;
            own[k] = (i < NIT);
            if (own[k]) {
                int plane = i / (TRR * GT);
                int r2    = i - plane * (TRR * GT);
                int rr_   = r2 / GT;
                int j     = r2 - rr_ * GT;
                int hh    = h0 - 3 + rr_;
                int gg    = gb + j;
                pl[k] = plane; rr[k] = rr_; jj[k] = j;
                valid[k] = ((unsigned)hh < (unsigned)H_) && ((unsigned)gg < 32u);
                const float4* p = pb + (size_t)plane * HW4_
                                + (valid[k] ? (hh * 32 + gg) : 0);
                #pragma unroll
                for (int c = 0; c < 4; ++c)
                    regs[k][c] = __ldg(p + c * cs);
            }
        }

        #pragma unroll
        for (int k = 0; k < 2; ++k) {
            if (own[k]) {
                float4 v = make_float4(0.f, 0.f, 0.f, 0.f);
                if (valid[k]) {
                    if (pl[k] == 0) {
                        v.x = (regs[k][0].x + regs[k][1].x + regs[k][2].x + regs[k][3].x) * inv;
                        v.y = (regs[k][0].y + regs[k][1].y + regs[k][2].y + regs[k][3].y) * inv;
                        v.z = (regs[k][0].z + regs[k][1].z + regs[k][2].z + regs[k][3].z) * inv;
                        v.w = (regs[k][0].w + regs[k][1].w + regs[k][2].w + regs[k][3].w) * inv;
                    } else {
                        v.x = fmaxf(fmaxf(regs[k][0].x, regs[k][1].x), fmaxf(regs[k][2].x, regs[k][3].x));
                        v.y = fmaxf(fmaxf(regs[k][0].y, regs[k][1].y), fmaxf(regs[k][2].y, regs[k][3].y));
                        v.z = fmaxf(fmaxf(regs[k][0].z, regs[k][1].z), fmaxf(regs[k][2].z, regs[k][3].z));
                        v.w = fmaxf(fmaxf(regs[k][0].w, regs[k][1].w), fmaxf(regs[k][2].w, regs[k][3].w));
                    }
                }
                sm[pl[k]][rr[k]][jj[k]] = v;
            }
        }
    }
    __syncthreads();

    if (threadIdx.x < 128) {
        int r = threadIdx.x >> 3;
        int j = threadIdx.x & 7;

        float acc0 = 0.f, acc1 = 0.f, acc2 = 0.f, acc3 = 0.f;

        #pragma unroll
        for (int ch = 0; ch < 2; ++ch) {
            const float* wp = ws + ch * 49;
            #pragma unroll
            for (int kh = 0; kh < 7; ++kh) {
                float4 lo  = sm[ch][r + kh][j];
                float4 mid = sm[ch][r + kh][j + 1];
                float4 hi  = sm[ch][r + kh][j + 2];
                float v[12] = { lo.x, lo.y, lo.z, lo.w,
                                mid.x, mid.y, mid.z, mid.w,
                                hi.x, hi.y, hi.z, hi.w };
                #pragma unroll
                for (int kw = 0; kw < 7; ++kw) {
                    float wv = wp[kh * 7 + kw];
                    acc0 = fmaf(v[kw + 1], wv, acc0);
                    acc1 = fmaf(v[kw + 2], wv, acc1);
                    acc2 = fmaf(v[kw + 3], wv, acc2);
                    acc3 = fmaf(v[kw + 4], wv, acc3);
                }
            }
        }

        float4 res;
        res.x = 1.0f / (1.0f + __expf(-acc0));
        res.y = 1.0f / (1.0f + __expf(-acc1));
        res.z = 1.0f / (1.0f + __expf(-acc2));
        res.w = 1.0f / (1.0f + __expf(-acc3));
        reinterpret_cast<float4*>(out)[(size_t)b * HW4_ + (h0 + r) * 32 + w0g + j] = res;
    }
}

// ---------------------------------------------------------------------------
// Persistent kernel v2: 512 blocks, ALL resident in one wave. Each block does
// exactly 2 reduce items (same batch, adjacent slices) -> balanced, full-BW
// streaming. Then grid-wide producer counters gate conv tiles (1 per block
// via ticket). Spin uses __nanosleep backoff; partials are L2-hot.
// ---------------------------------------------------------------------------
__global__ __launch_bounds__(256, 5)
void fused_persistent_kernel(const float* __restrict__ x,
                             const float* __restrict__ wgt,
                             float* __restrict__ out) {
    __shared__ float4 sm[2][TRR][GT];
    __shared__ float  ws[98];
    __shared__ int    s_tile;

    if (threadIdx.x < 98) ws[threadIdx.x] = __ldg(wgt + threadIdx.x);

    int bid = blockIdx.x;

    // Reduce phase: items 2*bid and 2*bid+1 (same batch: 64 items per batch)
    do_reduce_item(x, 2 * bid);
    do_reduce_item(x, 2 * bid + 1);

    __threadfence();                         // stores visible device-wide
    __syncthreads();
    if (threadIdx.x == 0)
        atomicAdd(&g_sync[(2 * bid) >> 6], 2);   // both items, one publish

    // Conv phase: batch-ordered ticket queue with throttled spin
    for (;;) {
        if (threadIdx.x == 0) s_tile = atomicAdd(&g_sync[B_], 1);
        __syncthreads();
        int t = s_tile;
        if (t >= NTILE) break;

        int tb = t >> 5;                     // tile's batch
        if (threadIdx.x == 0) {
            while (*(volatile int*)&g_sync[tb] < 64)
                __nanosleep(128);            // backoff: no L2 hammering
        }
        __syncthreads();
        __threadfence();                     // acquire ordering for partials

        do_conv_tile(t, ws, sm, out);
        __syncthreads();                     // sm + s_tile reuse safe
    }
}

extern "C" void kernel_launch(void* const* d_in, const int* in_sizes, int n_in,
                              void* d_out, int out_size) {
    const float* x = (const float*)d_in[0];
    const float* w = (const float*)d_in[1];
    float* out = (float*)d_out;

    // Reset counters + ticket each launch/replay (async memset node, no alloc)
    void* sync_addr = nullptr;
    cudaGetSymbolAddress(&sync_addr, g_sync);
    cudaMemsetAsync(sync_addr, 0, sizeof(int) * (B_ + 1));

    fused_persistent_kernel<<<NBLK, 256>>>(x, w, out);
}

// round 16
// speedup vs baseline: 1.0988x; 1.0819x over previous
#include <cuda_runtime.h>
#include <cuda_bf16.h>
#include <math.h>

// Problem constants: x [16, 256, 128, 128] fp32, w [1, 2, 7, 7] fp32
// out [16, 1, 128, 128] fp32
#define B_  16
#define C_  256
#define H_  128
#define W_  128
#define HW_ (H_ * W_)          // 16384
#define HW4_ (HW_ / 4)         // 4096 float4 groups per plane
#define NCHUNK 4
#define CPC (C_ / NCHUNK)      // 64 channels per chunk

// Fused-kernel tiling: 16 rows x 32 cols per block -> 512 blocks.
#define HT  16                 // output rows per tile
#define TRR (HT + 6)           // input rows incl. vertical halo = 22
#define GT  10                 // float4 groups incl. horizontal halo (8 + 2)
#define NIT (2 * TRR * GT)     // 440 combine items per block

typedef unsigned long long u64_t;

// Scratch: per-chunk partials [chunk][B][2][HW] (sum plane, max plane) = 8 MB
__device__ float g_part[NCHUNK * B_ * 2 * HW_];

// L2 evict-last store via cache-hint policy (ptxas rejects the direct
// .L2::evict_last modifier on v4.f32; createpolicy + cache_hint is legal).
__device__ __forceinline__ void st_evict_last(float4* p, float4 v, u64_t pol) {
    asm volatile("st.global.L2::cache_hint.v4.f32 [%0], {%1, %2, %3, %4}, %5;"
                 :: "l"(p), "f"(v.x), "f"(v.y), "f"(v.z), "f"(v.w), "l"(pol)
                 : "memory");
}

__device__ __forceinline__ u64_t mk_evict_last_policy() {
    u64_t pol;
    asm volatile("createpolicy.fractional.L2::evict_last.b64 %0, 1.0;" : "=l"(pol));
    return pol;
}

// ---------------------------------------------------------------------------
// Kernel 1: partial channel sum + max over a 64-channel chunk.
// 1024 blocks = proven 82.5% DRAM-active config. __ldcs marks the big stream
// evict-first; partials stored evict-last so the fused kernel L2-hits them.
// ---------------------------------------------------------------------------
__global__ __launch_bounds__(256) void reduce_partial_kernel(const float* __restrict__ x) {
    int chunk = blockIdx.x >> 8;                       // 0..3
    int t = ((blockIdx.x & 255) << 8) + threadIdx.x;   // 0..65535
    int b   = t >> 12;        // / 4096
    int sp4 = t & 4095;       // float4 group within plane

    const float4* base = reinterpret_cast<const float4*>(x)
                       + (size_t)b * C_ * HW4_ + (size_t)chunk * CPC * HW4_ + sp4;

    float4 sum = make_float4(0.f, 0.f, 0.f, 0.f);
    float4 mx  = make_float4(-INFINITY, -INFINITY, -INFINITY, -INFINITY);

    #pragma unroll 8
    for (int c = 0; c < CPC; ++c) {
        float4 v = __ldcs(base + c * HW4_);            // streaming, evict-first
        sum.x += v.x; sum.y += v.y; sum.z += v.z; sum.w += v.w;
        mx.x = fmaxf(mx.x, v.x); mx.y = fmaxf(mx.y, v.y);
        mx.z = fmaxf(mx.z, v.z); mx.w = fmaxf(mx.w, v.w);
    }

    u64_t pol = mk_evict_last_policy();
    float4* p_sum = reinterpret_cast<float4*>(g_part)
                  + (size_t)chunk * B_ * 2 * HW4_ + (size_t)b * 2 * HW4_ + sp4;
    st_evict_last(p_sum,        sum, pol);
    st_evict_last(p_sum + HW4_, mx,  pol);
}

// ---------------------------------------------------------------------------
// Kernel 2 (fused): combine 4 chunk partials (now L2-hot) -> mean/max tile in
// smem (vert+horiz halo, zero-padded), then 7x7 2-ch conv + sigmoid, 4-wide
// register blocked. 512 blocks x 256 threads; block = 16 rows x 32 cols.
// ---------------------------------------------------------------------------
__global__ __launch_bounds__(256) void fused_combine_conv_kernel(const float* __restrict__ wgt,
                                                                 float* __restrict__ out) {
    __shared__ float4 sm[2][TRR][GT];  // 7 KB
    __shared__ float  ws[98];

    if (threadIdx.x < 98) ws[threadIdx.x] = __ldg(wgt + threadIdx.x);

    int bid = blockIdx.x;
    int b   = bid >> 5;                // batch
    int rem = bid & 31;
    int ht  = rem >> 2;                // 0..7  (h tile)
    int wt  = rem & 3;                 // 0..3  (w tile)
    int h0  = ht * HT;                 // first output row
    int w0g = wt * 8;                  // first output float4 group
    int gb  = w0g - 1;                 // first halo group (may be -1)

    const size_t cs = (size_t)B_ * 2 * HW4_;   // chunk stride in float4
    const float inv = 1.0f / (float)C_;
    const float4* pb = reinterpret_cast<const float4*>(g_part) + (size_t)b * 2 * HW4_;

    // ---- Combine phase: 440 items, threads own i = tid and tid+256 ----
    {
        float4 regs[2][4];
        int    pl[2], rr[2], jj[2];
        bool   valid[2], own[2];

        #pragma unroll
        for (int k = 0; k < 2; ++k) {
            int i = threadIdx.x + k * 256;
            own[k] = (i < NIT);
            if (own[k]) {
                int plane = i / (TRR * GT);            // boundary at 220
                int r2    = i - plane * (TRR * GT);
                int r     = r2 / GT;
                int j     = r2 - r * GT;
                int hh    = h0 - 3 + r;
                int gg    = gb + j;
                pl[k] = plane; rr[k] = r; jj[k] = j;
                valid[k] = ((unsigned)hh < (unsigned)H_) && ((unsigned)gg < 32u);
                const float4* p = pb + (size_t)plane * HW4_
                                + (valid[k] ? (hh * 32 + gg) : 0);
                #pragma unroll
                for (int c = 0; c < 4; ++c)
                    regs[k][c] = __ldg(p + c * cs);
            }
        }

        #pragma unroll
        for (int k = 0; k < 2; ++k) {
            if (own[k]) {
                float4 v = make_float4(0.f, 0.f, 0.f, 0.f);
                if (valid[k]) {
                    if (pl[k] == 0) {
                        v.x = (regs[k][0].x + regs[k][1].x + regs[k][2].x + regs[k][3].x) * inv;
                        v.y = (regs[k][0].y + regs[k][1].y + regs[k][2].y + regs[k][3].y) * inv;
                        v.z = (regs[k][0].z + regs[k][1].z + regs[k][2].z + regs[k][3].z) * inv;
                        v.w = (regs[k][0].w + regs[k][1].w + regs[k][2].w + regs[k][3].w) * inv;
                    } else {
                        v.x = fmaxf(fmaxf(regs[k][0].x, regs[k][1].x), fmaxf(regs[k][2].x, regs[k][3].x));
                        v.y = fmaxf(fmaxf(regs[k][0].y, regs[k][1].y), fmaxf(regs[k][2].y, regs[k][3].y));
                        v.z = fmaxf(fmaxf(regs[k][0].z, regs[k][1].z), fmaxf(regs[k][2].z, regs[k][3].z));
                        v.w = fmaxf(fmaxf(regs[k][0].w, regs[k][1].w), fmaxf(regs[k][2].w, regs[k][3].w));
                    }
                }
                sm[pl[k]][rr[k]][jj[k]] = v;
            }
        }
    }
    __syncthreads();

    // ---- Conv phase: threads 0..127 -> (row r, output group j), 4 px each ----
    if (threadIdx.x < 128) {
        int r = threadIdx.x >> 3;          // 0..15
        int j = threadIdx.x & 7;           // 0..7

        float acc0 = 0.f, acc1 = 0.f, acc2 = 0.f, acc3 = 0.f;

        #pragma unroll
        for (int ch = 0; ch < 2; ++ch) {
            const float* wp = ws + ch * 49;
            #pragma unroll
            for (int kh = 0; kh < 7; ++kh) {
                float4 lo  = sm[ch][r + kh][j];        // halo (zero-padded)
                float4 mid = sm[ch][r + kh][j + 1];
                float4 hi  = sm[ch][r + kh][j + 2];
                float v[12] = { lo.x, lo.y, lo.z, lo.w,
                                mid.x, mid.y, mid.z, mid.w,
                                hi.x, hi.y, hi.z, hi.w };
                #pragma unroll
                for (int kw = 0; kw < 7; ++kw) {
                    float wv = wp[kh * 7 + kw];
                    acc0 = fmaf(v[kw + 1], wv, acc0);
                    acc1 = fmaf(v[kw + 2], wv, acc1);
                    acc2 = fmaf(v[kw + 3], wv, acc2);
                    acc3 = fmaf(v[kw + 4], wv, acc3);
                }
            }
        }

        float4 res;
        res.x = 1.0f / (1.0f + __expf(-acc0));
        res.y = 1.0f / (1.0f + __expf(-acc1));
        res.z = 1.0f / (1.0f + __expf(-acc2));
        res.w = 1.0f / (1.0f + __expf(-acc3));
        reinterpret_cast<float4*>(out)[(size_t)b * HW4_ + (h0 + r) * 32 + w0g + j] = res;
    }
}

extern "C" void kernel_launch(void* const* d_in, const int* in_sizes, int n_in,
                              void* d_out, int out_size) {
    const float* x = (const float*)d_in[0];
    const float* w = (const float*)d_in[1];
    float* out = (float*)d_out;

    reduce_partial_kernel<<<NCHUNK * 256, 256>>>(x);       // 1024 blocks
    fused_combine_conv_kernel<<<512, 256>>>(w, out);       // 512 blocks
}